// round 6
// baseline (speedup 1.0000x reference)
#include <cuda_runtime.h>
#include <math.h>

// Fused block-DCT + soft-histogram, v6: register headroom for pipelining,
// vectorized basis load (smaller front LDG burst), streamlined scatter.
//
// Grid (16 batch, 32 block-rows, 2 k-halves) = 1024 CTAs x 128 threads.
// Thread = (blk = lane, 8 consecutive k) as 4 packed f32x2 accumulators.
// fma.rn.f32x2 = two independent fma.rn.f32 -> each k's ascending-p chain is
// bit-identical to v1-v5 (rel_err ~7e-9).
//
// Histogram: gamma=1e6 saturates sigmoids to exact 0/1 except within ~3e-5
// of an integer threshold -> hard count (+1/1024, exact dyadic). One
// __match_any_sync per k: soft-edge lanes get unique sentinel keys and take
// a cold exact-sigmoid path; hard lanes aggregate into one REDG per bin.

#define NBINS   120
#define INV1024 (1.0f / 1024.0f)
#define PSTRIDE 68   // 68 % 32 == 4 -> conflict-free float4 reads over p

#define FMA_F32X2(d, a, b, c) \
    asm("fma.rn.f32x2 %0, %1, %2, %3;" \
        : "=l"(d) : "l"(a), "l"(b), "l"(c))

#define PACK_DUP_F32X2(d, f) \
    asm("mov.b64 %0, {%1, %1};" : "=l"(d) : "r"(__float_as_uint(f)))

__global__ void __launch_bounds__(128, 5)
dct_hist_kernel(const float* __restrict__ in,
                const float* __restrict__ basis,
                float* __restrict__ out)
{
    __shared__ __align__(16) float B_s[64 * 32];       // basis [p][kk], 8 KB
    __shared__ __align__(16) float in_s[32 * PSTRIDE]; // input [blk][p], 8.7 KB

    const int b   = blockIdx.x;   // batch
    const int row = blockIdx.y;   // block-row 0..31
    const int kh  = blockIdx.z;   // k-half 0/1
    const int tid = threadIdx.x;

    // Load basis half, vectorized: 4 LDG.128 per thread.
    // B_s[p*32 + kk] = basis[p*64 + kh*32 + kk]
    #pragma unroll
    for (int i = tid; i < 512; i += 128) {
        int p  = i >> 3;          // 0..63
        int kq = (i & 7) << 2;    // 0,4,...,28
        float4 v = *reinterpret_cast<const float4*>(
            basis + (p << 6) + (kh << 5) + kq);
        *reinterpret_cast<float4*>(&B_s[(p << 5) + kq]) = v;
    }

    // Load input strip: 8 pixel rows x 256 cols -> in_s[blk][p] (4 LDG.128/thr)
    const float4* src = reinterpret_cast<const float4*>(
        in + ((size_t)b * 256 + (size_t)row * 8) * 256);
    #pragma unroll
    for (int i = tid; i < 512; i += 128) {
        float4 v  = src[i];
        int r     = i >> 6;              // pixel row 0..7 (= dx)
        int c0    = (i & 63) << 2;       // col 0..252 step 4
        int blk   = c0 >> 3;             // 0..31
        int p     = (r << 3) | (c0 & 7); // p = dx*8 + dy, multiple of 4
        *reinterpret_cast<float4*>(&in_s[blk * PSTRIDE + p]) = v;
    }
    __syncthreads();

    // DCT: thread -> (blk = lane, 8 consecutive k at warp*8)
    const int lane = tid & 31;
    const int k0   = (tid >> 5) << 3;   // 0,8,16,24 (uniform per warp)

    unsigned long long acc0 = 0ull, acc1 = 0ull, acc2 = 0ull, acc3 = 0ull;
    const float* arow = in_s + lane * PSTRIDE;

    #pragma unroll
    for (int q = 0; q < 16; q++) {
        float4 a = *reinterpret_cast<const float4*>(arow + (q << 2)); // 4 p's
        #pragma unroll
        for (int s = 0; s < 4; s++) {
            int p    = (q << 2) + s;
            float av = (s == 0) ? a.x : (s == 1) ? a.y : (s == 2) ? a.z : a.w;
            unsigned long long av2;
            PACK_DUP_F32X2(av2, av);
            const ulonglong2* bp =
                reinterpret_cast<const ulonglong2*>(B_s + (p << 5) + k0);
            ulonglong2 b01 = bp[0];   // k0..k0+3
            ulonglong2 b23 = bp[1];   // k0+4..k0+7
            FMA_F32X2(acc0, av2, b01.x, acc0);
            FMA_F32X2(acc1, av2, b01.y, acc1);
            FMA_F32X2(acc2, av2, b23.x, acc2);
            FMA_F32X2(acc3, av2, b23.y, acc3);
        }
    }

    // Unpack the 8 per-k results
    float vals[8];
    {
        unsigned lo, hi;
        asm("mov.b64 {%0, %1}, %2;" : "=r"(lo), "=r"(hi) : "l"(acc0));
        vals[0] = __uint_as_float(lo); vals[1] = __uint_as_float(hi);
        asm("mov.b64 {%0, %1}, %2;" : "=r"(lo), "=r"(hi) : "l"(acc1));
        vals[2] = __uint_as_float(lo); vals[3] = __uint_as_float(hi);
        asm("mov.b64 {%0, %1}, %2;" : "=r"(lo), "=r"(hi) : "l"(acc2));
        vals[4] = __uint_as_float(lo); vals[5] = __uint_as_float(hi);
        asm("mov.b64 {%0, %1}, %2;" : "=r"(lo), "=r"(hi) : "l"(acc3));
        vals[6] = __uint_as_float(lo); vals[7] = __uint_as_float(hi);
    }

    // Scatter: one match per k; soft lanes take unique sentinel keys.
    float* outb = out + (size_t)b * NBINS * 64;

    #pragma unroll
    for (int j = 0; j < 8; j++) {
        float v  = vals[j];
        float fl = floorf(v);
        float d  = v - fl;                 // [0,1)
        int   ti = (int)fl + 60;
        const int kk = (kh << 5) + k0 + j; // uniform per warp

        bool soft = fabsf(d - 0.5f) > (0.5f - 3e-5f);
        int key   = soft ? (0x10000 | lane) : ti;
        unsigned grp = __match_any_sync(0xffffffffu, key);

        if (!soft) {
            if (lane == __ffs(grp) - 1 && (unsigned)ti < (unsigned)NBINS)
                atomicAdd(&outb[ti * 64 + kk], (float)__popc(grp) * INV1024);
        } else {
            // Cold path: exact fp32 sigmoids at the two nearest thresholds.
            float z0 = 1e6f * (v - (float)(ti - 60));
            float z1 = 1e6f * (v - (float)(ti - 59));
            float s0 = (z0 >= 30.0f) ? 1.0f : (1.0f / (1.0f + expf(-z0)));
            float s1;
            if (z1 <= -30.0f) s1 = 0.0f;
            else { float e = expf(z1); s1 = e / (1.0f + e); }

            float w_lo  = (1.0f - s0) * INV1024;  // bin ti-1
            float w_mid = (s0 - s1)   * INV1024;  // bin ti
            float w_hi  = s1          * INV1024;  // bin ti+1
            if ((unsigned)(ti - 1) < (unsigned)NBINS && w_lo != 0.0f)
                atomicAdd(&outb[(ti - 1) * 64 + kk], w_lo);
            if ((unsigned)ti < (unsigned)NBINS && w_mid != 0.0f)
                atomicAdd(&outb[ti * 64 + kk], w_mid);
            if ((unsigned)(ti + 1) < (unsigned)NBINS && w_hi != 0.0f)
                atomicAdd(&outb[(ti + 1) * 64 + kk], w_hi);
        }
    }
}

extern "C" void kernel_launch(void* const* d_in, const int* in_sizes, int n_in,
                              void* d_out, int out_size)
{
    const float* in    = (const float*)d_in[0];   // [16,256,256,1]
    const float* basis = (const float*)d_in[1];   // [8,8,1,64]
    float* out = (float*)d_out;                   // [16,120,64,1]
    (void)in_sizes; (void)n_in;

    cudaMemsetAsync(d_out, 0, (size_t)out_size * sizeof(float), 0);

    dim3 grid(16, 32, 2);
    dct_hist_kernel<<<grid, 128>>>(in, basis, out);
}

// round 7
// speedup vs baseline: 1.0021x; 1.0021x over previous
#include <cuda_runtime.h>
#include <math.h>

// Fused block-DCT + soft-histogram, v7: cp.async double-buffered strips to
// overlap DRAM fetch with compute (R3-R6 were DRAM-latency-exposure bound:
// 4.2 MB at ~350 GB/s == the entire 12.2us kernel).
//
// Grid (16 batch, 16 strip-pairs) = 256 CTAs x 256 threads, 2 strips each.
// Warp w (0..7) -> k in [8w, 8w+8) as 4 packed f32x2 accumulators; lane=blk.
// fma.rn.f32x2 = two independent fma.rn.f32 -> each k's ascending-p chain is
// bit-identical to v1-v6 (rel_err ~7e-9).
//
// Histogram: gamma=1e6 saturates sigmoids to exact 0/1 except within ~3e-5 of
// an integer threshold -> hard count (+1/1024, exact dyadic), warp-aggregated
// via __match_any_sync into one global atomicAdd per distinct bin; rare soft
// lanes take unique sentinel keys and compute the boundary sigmoids exactly.

#define NBINS   120
#define INV1024 (1.0f / 1024.0f)
#define PSTRIDE 68   // 68 % 32 == 4 -> conflict-free float4 reads over p

#define FMA_F32X2(d, a, b, c) \
    asm("fma.rn.f32x2 %0, %1, %2, %3;" \
        : "=l"(d) : "l"(a), "l"(b), "l"(c))

#define PACK_DUP_F32X2(d, f) \
    asm("mov.b64 %0, {%1, %1};" : "=l"(d) : "r"(__float_as_uint(f)))

#define CP_ASYNC16(dst_u32, src) \
    asm volatile("cp.async.cg.shared.global [%0], [%1], 16;" \
                 :: "r"(dst_u32), "l"(src))
#define CP_COMMIT()  asm volatile("cp.async.commit_group;")
#define CP_WAIT(n)   asm volatile("cp.async.wait_group %0;" :: "n"(n))

__global__ void __launch_bounds__(256, 3)
dct_hist_kernel(const float* __restrict__ in,
                const float* __restrict__ basis,
                float* __restrict__ out)
{
    __shared__ __align__(16) float B_s[64 * 64];           // basis [p][k], 16 KB
    __shared__ __align__(16) float in_s[2][32 * PSTRIDE];  // 2 strip buffers

    const int b    = blockIdx.x;   // batch
    const int rp   = blockIdx.y;   // strip pair 0..15 (strips 2*rp, 2*rp+1)
    const int tid  = threadIdx.x;
    const int lane = tid & 31;
    const int k0   = (tid >> 5) << 3;   // 0..56, uniform per warp

    // ---- Prologue: async-stage basis + strip0 (group A), strip1 (group B)
    // Basis: 1024 float4, 4 per thread (coalesced; [p][k] layout is direct).
    #pragma unroll
    for (int i = tid; i < 1024; i += 256) {
        unsigned dst = (unsigned)__cvta_generic_to_shared(&B_s[i << 2]);
        CP_ASYNC16(dst, basis + (i << 2));
    }
    // Strip staging helper indices: 512 float4 per strip, 2 per thread.
    const float4* src0 = reinterpret_cast<const float4*>(
        in + ((size_t)b * 256 + (size_t)(rp * 2 + 0) * 8) * 256);
    const float4* src1 = reinterpret_cast<const float4*>(
        in + ((size_t)b * 256 + (size_t)(rp * 2 + 1) * 8) * 256);

    #pragma unroll
    for (int i = tid; i < 512; i += 256) {
        int r   = i >> 6;               // pixel row 0..7 (= dx)
        int c0  = (i & 63) << 2;        // col 0..252 step 4
        int blk = c0 >> 3;              // 0..31
        int p   = (r << 3) | (c0 & 7);  // p = dx*8 + dy, multiple of 4
        unsigned dst = (unsigned)__cvta_generic_to_shared(
            &in_s[0][blk * PSTRIDE + p]);
        CP_ASYNC16(dst, src0 + i);
    }
    CP_COMMIT();   // group: basis + strip0

    #pragma unroll
    for (int i = tid; i < 512; i += 256) {
        int r   = i >> 6;
        int c0  = (i & 63) << 2;
        int blk = c0 >> 3;
        int p   = (r << 3) | (c0 & 7);
        unsigned dst = (unsigned)__cvta_generic_to_shared(
            &in_s[1][blk * PSTRIDE + p]);
        CP_ASYNC16(dst, src1 + i);
    }
    CP_COMMIT();   // group: strip1

    float* outb = out + (size_t)b * NBINS * 64;

    #pragma unroll
    for (int s = 0; s < 2; s++) {
        if (s == 0) { CP_WAIT(1); } else { CP_WAIT(0); }
        __syncthreads();

        // ---- DCT mainloop on buffer s (ascending-p, bit-exact chains)
        unsigned long long acc0 = 0ull, acc1 = 0ull, acc2 = 0ull, acc3 = 0ull;
        const float* arow = in_s[s] + lane * PSTRIDE;

        #pragma unroll
        for (int q = 0; q < 16; q++) {
            float4 a = *reinterpret_cast<const float4*>(arow + (q << 2));
            #pragma unroll
            for (int t = 0; t < 4; t++) {
                int p    = (q << 2) + t;
                float av = (t == 0) ? a.x : (t == 1) ? a.y
                         : (t == 2) ? a.z : a.w;
                unsigned long long av2;
                PACK_DUP_F32X2(av2, av);
                const ulonglong2* bp =
                    reinterpret_cast<const ulonglong2*>(B_s + (p << 6) + k0);
                ulonglong2 b01 = bp[0];   // k0..k0+3
                ulonglong2 b23 = bp[1];   // k0+4..k0+7
                FMA_F32X2(acc0, av2, b01.x, acc0);
                FMA_F32X2(acc1, av2, b01.y, acc1);
                FMA_F32X2(acc2, av2, b23.x, acc2);
                FMA_F32X2(acc3, av2, b23.y, acc3);
            }
        }

        // ---- Unpack + scatter (overlaps strip1 cp.async still in flight)
        float vals[8];
        {
            unsigned lo, hi;
            asm("mov.b64 {%0, %1}, %2;" : "=r"(lo), "=r"(hi) : "l"(acc0));
            vals[0] = __uint_as_float(lo); vals[1] = __uint_as_float(hi);
            asm("mov.b64 {%0, %1}, %2;" : "=r"(lo), "=r"(hi) : "l"(acc1));
            vals[2] = __uint_as_float(lo); vals[3] = __uint_as_float(hi);
            asm("mov.b64 {%0, %1}, %2;" : "=r"(lo), "=r"(hi) : "l"(acc2));
            vals[4] = __uint_as_float(lo); vals[5] = __uint_as_float(hi);
            asm("mov.b64 {%0, %1}, %2;" : "=r"(lo), "=r"(hi) : "l"(acc3));
            vals[6] = __uint_as_float(lo); vals[7] = __uint_as_float(hi);
        }

        #pragma unroll
        for (int j = 0; j < 8; j++) {
            float v  = vals[j];
            float fl = floorf(v);
            float d  = v - fl;                 // [0,1)
            int   ti = (int)fl + 60;
            const int kk = k0 + j;             // uniform per warp

            bool soft = fabsf(d - 0.5f) > (0.5f - 3e-5f);
            int key   = soft ? (0x10000 | lane) : ti;
            unsigned grp = __match_any_sync(0xffffffffu, key);

            if (!soft) {
                if (lane == __ffs(grp) - 1 && (unsigned)ti < (unsigned)NBINS)
                    atomicAdd(&outb[ti * 64 + kk],
                              (float)__popc(grp) * INV1024);
            } else {
                float z0 = 1e6f * (v - (float)(ti - 60));
                float z1 = 1e6f * (v - (float)(ti - 59));
                float s0 = (z0 >= 30.0f) ? 1.0f : (1.0f / (1.0f + expf(-z0)));
                float s1;
                if (z1 <= -30.0f) s1 = 0.0f;
                else { float e = expf(z1); s1 = e / (1.0f + e); }

                float w_lo  = (1.0f - s0) * INV1024;  // bin ti-1
                float w_mid = (s0 - s1)   * INV1024;  // bin ti
                float w_hi  = s1          * INV1024;  // bin ti+1
                if ((unsigned)(ti - 1) < (unsigned)NBINS && w_lo != 0.0f)
                    atomicAdd(&outb[(ti - 1) * 64 + kk], w_lo);
                if ((unsigned)ti < (unsigned)NBINS && w_mid != 0.0f)
                    atomicAdd(&outb[ti * 64 + kk], w_mid);
                if ((unsigned)(ti + 1) < (unsigned)NBINS && w_hi != 0.0f)
                    atomicAdd(&outb[(ti + 1) * 64 + kk], w_hi);
            }
        }

        if (s == 0) __syncthreads();   // protect buffer reuse ordering
    }
}

extern "C" void kernel_launch(void* const* d_in, const int* in_sizes, int n_in,
                              void* d_out, int out_size)
{
    const float* in    = (const float*)d_in[0];   // [16,256,256,1]
    const float* basis = (const float*)d_in[1];   // [8,8,1,64]
    float* out = (float*)d_out;                   // [16,120,64,1]
    (void)in_sizes; (void)n_in;

    cudaMemsetAsync(d_out, 0, (size_t)out_size * sizeof(float), 0);

    dim3 grid(16, 16);
    dct_hist_kernel<<<grid, 256>>>(in, basis, out);
}